// round 16
// baseline (speedup 1.0000x reference)
#include <cuda_runtime.h>
#include <cuda_bf16.h>

#define TPB 512
#define NWARP (TPB / 32)   // 16

// R13 optimum with ONE experimental change: default (cache-all) loads instead
// of .cs loads — the last unbracketed policy axis. Stores stay .cs (bracketed:
// default -3%, .wt -2.5%). Plus a free ALU trim: row%S via mask when S is a
// power of two (computed host-side). Everything else identical to R13:
// interleaved 16B lane stride (512B full-sector wavefronts), packed s16x2
// __vmaxs2 single block scan, TPB=512, natural regs, one row per CTA.
// idx_mask committed int32 (verified R7 via rel_err + HBM traffic).
__global__ __launch_bounds__(TPB) void seg_mask_kernel(
    const float* __restrict__ x,
    const int*   __restrict__ idx_mask,       // [rows*T] int32 0/1
    const int*   __restrict__ mask_size,      // [S]
    const int*   __restrict__ mask_value,     // scalar
    float* __restrict__ out,                  // [rows*T]
    float* __restrict__ mask_out,             // [rows*T] or nullptr
    int S, int s_mask, int T)                 // s_mask = S-1 if pow2 else -1
{
    const int tid  = threadIdx.x;
    const int lane = tid & 31, wid = tid >> 5;
    const int row  = blockIdx.x;              // row = b*S + s
    const int s    = (s_mask >= 0) ? (row & s_mask) : (row % S);
    const long long base = (long long)row * T;
    const int half = T >> 1;                  // 2048
    const int t0a  = tid * 4;                 // first-half positions
    const int t0b  = half + tid * 4;          // second-half positions

    // ---- front-batch ALL loads, fully coalesced; DEFAULT cache policy ----
    int4   ia = *(const int4*)(idx_mask + base + t0a);
    int4   ib = *(const int4*)(idx_mask + base + t0b);
    float4 xa = *(const float4*)(x + base + t0a);
    float4 xb = *(const float4*)(x + base + t0b);

    unsigned bitsa =
          ((unsigned)(ia.x != 0) << 0) | ((unsigned)(ia.y != 0) << 1)
        | ((unsigned)(ia.z != 0) << 2) | ((unsigned)(ia.w != 0) << 3);
    unsigned bitsb =
          ((unsigned)(ib.x != 0) << 0) | ((unsigned)(ib.y != 0) << 1)
        | ((unsigned)(ib.z != 0) << 2) | ((unsigned)(ib.w != 0) << 3);

    const int   m  = __ldg(mask_size + s);
    const float mv = (float)__ldg(mask_value);

    // ---- local "last start index" per half, packed s16x2 (a=hi, b=lo) ----
    int la = bitsa ? (t0a + 31 - __clz(bitsa)) : -1;   // [-1, 2047]
    int lb = bitsb ? (t0b + 31 - __clz(bitsb)) : -1;   // [-1, 4095]
    unsigned p = ((unsigned)(la & 0xFFFF) << 16) | (unsigned)(lb & 0xFFFF);

    // ---- single packed block-wide max-scan ----
    #pragma unroll
    for (int off = 1; off < 32; off <<= 1) {
        unsigned u = __shfl_up_sync(0xffffffffu, p, off);
        if (lane >= off) p = __vmaxs2(p, u);
    }
    __shared__ unsigned wmax[NWARP];
    if (lane == 31) wmax[wid] = p;
    __syncthreads();
    unsigned incl_prev = __shfl_up_sync(0xffffffffu, p, 1);
    unsigned excl = (lane == 0) ? 0xFFFFFFFFu : incl_prev;  // (-1,-1)
    int tot_a = -1;                           // block-wide max of first half
    #pragma unroll
    for (int w = 0; w < NWARP; w++) {
        unsigned wm = wmax[w];
        if (w < wid) excl = __vmaxs2(excl, wm);
        tot_a = max(tot_a, (int)((short)(wm >> 16)));
    }
    int excl_a = (int)((short)(excl >> 16));
    int excl_b = max((int)((short)(excl & 0xFFFF)), tot_a);

    // ---- compute out / mask for both halves ----
    float4 oa, ob, ma, mb;
    {
        const float* xp = (const float*)&xa;
        float* op = (float*)&oa; float* mp = (float*)&ma;
        int cur = excl_a;
        #pragma unroll
        for (int i = 0; i < 4; i++) {
            int t = t0a + i;
            if ((bitsa >> i) & 1u) cur = t;
            int lo = t - m; if (lo < 0) lo = 0;
            bool msk = (cur >= lo);
            mp[i] = msk ? 1.0f : 0.0f;
            op[i] = msk ? mv : xp[i];
        }
    }
    {
        const float* xp = (const float*)&xb;
        float* op = (float*)&ob; float* mp = (float*)&mb;
        int cur = excl_b;
        #pragma unroll
        for (int i = 0; i < 4; i++) {
            int t = t0b + i;
            if ((bitsb >> i) & 1u) cur = t;
            int lo = t - m; if (lo < 0) lo = 0;
            bool msk = (cur >= lo);
            mp[i] = msk ? 1.0f : 0.0f;
            op[i] = msk ? mv : xp[i];
        }
    }

    // ---- grouped, fully-coalesced .cs stores (bracketed optimum) ----
    __stcs((float4*)(out + base + t0a), oa);
    __stcs((float4*)(out + base + t0b), ob);
    if (mask_out) {
        __stcs((float4*)(mask_out + base + t0a), ma);
        __stcs((float4*)(mask_out + base + t0b), mb);
    }
}

extern "C" void kernel_launch(void* const* d_in, const int* in_sizes, int n_in,
                              void* d_out, int out_size) {
    const float* x     = (const float*)d_in[0];
    const int*   idx   = (const int*)d_in[1];
    const int*   msize = (const int*)d_in[2];
    const int*   mval  = (const int*)d_in[3];
    float* out = (float*)d_out;

    const int T = 4096;
    const int N = in_sizes[0];          // B*S*T
    const int S = in_sizes[2];          // 128
    const int rows = N / T;             // B*S = 8192

    // Power-of-two fast path for row % S.
    const int s_mask = ((S & (S - 1)) == 0) ? (S - 1) : -1;

    // Tuple output (out, mask) -> concatenated float32 if out_size covers both.
    float* mask_out = (out_size >= 2 * N) ? (out + (long long)N) : nullptr;

    seg_mask_kernel<<<rows, TPB>>>(x, idx, msize, mval, out, mask_out,
                                   S, s_mask, T);
}

// round 17
// speedup vs baseline: 1.0466x; 1.0466x over previous
#include <cuda_runtime.h>
#include <cuda_bf16.h>

#define TPB 512
#define NWARP (TPB / 32)   // 16

// FINAL — R13 measured optimum (wall 81.6us, kernel 77.3us, 79.0% DRAM,
// 6.26 TB/s on the information-theoretic-minimum 536MB 50/50 R/W mix ==
// the HBM turnaround ceiling for this pattern). Every axis bracketed:
// - .cs on ALL streams (loads: default -3%; stores: default -3%, .wt -2.5%).
// - One row per CTA; thread tid owns [4*tid,4*tid+4) of each half-row.
//   Lane stride 16B -> every LDG.128/STG.128 wavefront is 512B fully
//   contiguous (full 32B sectors; blocked 32B-stride layout was -6%).
// - Both halves' last-start max-scans packed s16x2, ONE block scan
//   (__vmaxs2); half-b carry = max(its exclusive prefix, half-a total).
// - TPB=512 (256 -3%, 1024 -9%); 2xfloat4/thread (1x -9%, 4x -8%);
//   natural regs 36 (forced 32 neutral-worse); one-shot grid (persistent ±0).
// - idx_mask committed as int32 0/1 (verified: rel_err==0 + measured HBM
//   traffic matches the int32 footprint, not 1-byte bool).
__global__ __launch_bounds__(TPB) void seg_mask_kernel(
    const float* __restrict__ x,
    const int*   __restrict__ idx_mask,       // [rows*T] int32 0/1
    const int*   __restrict__ mask_size,      // [S]
    const int*   __restrict__ mask_value,     // scalar
    float* __restrict__ out,                  // [rows*T]
    float* __restrict__ mask_out,             // [rows*T] or nullptr
    int S, int T)
{
    const int tid  = threadIdx.x;
    const int lane = tid & 31, wid = tid >> 5;
    const int row  = blockIdx.x;              // row = b*S + s
    const int s    = row % S;
    const long long base = (long long)row * T;
    const int half = T >> 1;                  // 2048
    const int t0a  = tid * 4;                 // first-half positions
    const int t0b  = half + tid * 4;          // second-half positions

    // ---- front-batch ALL loads, fully coalesced (lane stride 16B) ----
    int4   ia = __ldcs((const int4*)(idx_mask + base + t0a));
    int4   ib = __ldcs((const int4*)(idx_mask + base + t0b));
    float4 xa = __ldcs((const float4*)(x + base + t0a));
    float4 xb = __ldcs((const float4*)(x + base + t0b));

    unsigned bitsa =
          ((unsigned)(ia.x != 0) << 0) | ((unsigned)(ia.y != 0) << 1)
        | ((unsigned)(ia.z != 0) << 2) | ((unsigned)(ia.w != 0) << 3);
    unsigned bitsb =
          ((unsigned)(ib.x != 0) << 0) | ((unsigned)(ib.y != 0) << 1)
        | ((unsigned)(ib.z != 0) << 2) | ((unsigned)(ib.w != 0) << 3);

    const int   m  = __ldg(mask_size + s);
    const float mv = (float)__ldg(mask_value);

    // ---- local "last start index" per half, packed s16x2 (a=hi, b=lo) ----
    int la = bitsa ? (t0a + 31 - __clz(bitsa)) : -1;   // [-1, 2047]
    int lb = bitsb ? (t0b + 31 - __clz(bitsb)) : -1;   // [-1, 4095]
    unsigned p = ((unsigned)(la & 0xFFFF) << 16) | (unsigned)(lb & 0xFFFF);

    // ---- single packed block-wide max-scan ----
    #pragma unroll
    for (int off = 1; off < 32; off <<= 1) {
        unsigned u = __shfl_up_sync(0xffffffffu, p, off);
        if (lane >= off) p = __vmaxs2(p, u);
    }
    __shared__ unsigned wmax[NWARP];
    if (lane == 31) wmax[wid] = p;
    __syncthreads();
    unsigned incl_prev = __shfl_up_sync(0xffffffffu, p, 1);
    unsigned excl = (lane == 0) ? 0xFFFFFFFFu : incl_prev;  // (-1,-1)
    int tot_a = -1;                           // block-wide max of first half
    #pragma unroll
    for (int w = 0; w < NWARP; w++) {
        unsigned wm = wmax[w];
        if (w < wid) excl = __vmaxs2(excl, wm);
        tot_a = max(tot_a, (int)((short)(wm >> 16)));
    }
    int excl_a = (int)((short)(excl >> 16));
    int excl_b = max((int)((short)(excl & 0xFFFF)), tot_a);

    // ---- compute out / mask for both halves ----
    float4 oa, ob, ma, mb;
    {
        const float* xp = (const float*)&xa;
        float* op = (float*)&oa; float* mp = (float*)&ma;
        int cur = excl_a;
        #pragma unroll
        for (int i = 0; i < 4; i++) {
            int t = t0a + i;
            if ((bitsa >> i) & 1u) cur = t;
            int lo = t - m; if (lo < 0) lo = 0;
            bool msk = (cur >= lo);
            mp[i] = msk ? 1.0f : 0.0f;
            op[i] = msk ? mv : xp[i];
        }
    }
    {
        const float* xp = (const float*)&xb;
        float* op = (float*)&ob; float* mp = (float*)&mb;
        int cur = excl_b;
        #pragma unroll
        for (int i = 0; i < 4; i++) {
            int t = t0b + i;
            if ((bitsb >> i) & 1u) cur = t;
            int lo = t - m; if (lo < 0) lo = 0;
            bool msk = (cur >= lo);
            mp[i] = msk ? 1.0f : 0.0f;
            op[i] = msk ? mv : xp[i];
        }
    }

    // ---- grouped, fully-coalesced streaming stores ----
    __stcs((float4*)(out + base + t0a), oa);
    __stcs((float4*)(out + base + t0b), ob);
    if (mask_out) {
        __stcs((float4*)(mask_out + base + t0a), ma);
        __stcs((float4*)(mask_out + base + t0b), mb);
    }
}

extern "C" void kernel_launch(void* const* d_in, const int* in_sizes, int n_in,
                              void* d_out, int out_size) {
    const float* x     = (const float*)d_in[0];
    const int*   idx   = (const int*)d_in[1];
    const int*   msize = (const int*)d_in[2];
    const int*   mval  = (const int*)d_in[3];
    float* out = (float*)d_out;

    const int T = 4096;
    const int N = in_sizes[0];          // B*S*T
    const int S = in_sizes[2];          // 128
    const int rows = N / T;             // B*S = 8192

    // Tuple output (out, mask) -> concatenated float32 if out_size covers both.
    float* mask_out = (out_size >= 2 * N) ? (out + (long long)N) : nullptr;

    seg_mask_kernel<<<rows, TPB>>>(x, idx, msize, mval, out, mask_out, S, T);
}